// round 9
// baseline (speedup 1.0000x reference)
#include <cuda_runtime.h>

// Bilateral filter, B=2 C=3 H=W=384, ksize=9, sigma=1.7.
// Density exp ~ minimax linear poly in u=(v-c)^2 on [0,1]; filter = separable
// 9-tap Gaussian moments M1,M2,M3:
//   den = b1*M2 + (-2*b1*c)*M1 + (b0+b1*c^2)*S2
//   num = b1*M3 + (-2*b1*c)*M2 + (b0+b1*c^2)*M1
// Tile 64x32 out, 72x40 halo. Per-moment smem planes (packed col-pair lanes
// store/load as u64, no transposes). Vertical pass split into two 2-row-pair
// groups to cap live registers; __launch_bounds__(256,4) -> 4 CTAs/SM.

#define TW   64
#define TH   32
#define HALO 4
#define SWX  72
#define SWXP 76          // raw row stride (16B-aligned)
#define SWY  40
#define KS   9

typedef unsigned long long u64;

// exp(-A*d*d), A = 1/(2*1.7^2)
#define G0f 1.00000000f
#define G1f 0.84112888f
#define G2f 0.50055313f
#define G3f 0.21074770f
#define G4f 0.06277701f
#define S2f 17.8963970f
// minimax linear for exp(-A*u), u in [0,1]
#define B0f 0.99828148f
#define B1f (-0.15887112f)

__device__ __forceinline__ u64 pack2(float lo, float hi) {
    u64 r; asm("mov.b64 %0, {%1,%2};" : "=l"(r) : "f"(lo), "f"(hi)); return r;
}
__device__ __forceinline__ void unpack2(u64 v, float& lo, float& hi) {
    asm("mov.b64 {%0,%1}, %2;" : "=f"(lo), "=f"(hi) : "l"(v));
}
__device__ __forceinline__ u64 fma2(u64 a, u64 b, u64 c) {
    u64 d; asm("fma.rn.f32x2 %0, %1, %2, %3;" : "=l"(d) : "l"(a), "l"(b), "l"(c)); return d;
}
__device__ __forceinline__ u64 mul2(u64 a, u64 b) {
    u64 d; asm("mul.rn.f32x2 %0, %1, %2;" : "=l"(d) : "l"(a), "l"(b)); return d;
}

__global__ __launch_bounds__(256, 4)
void bilateral9_kernel(const float* __restrict__ x, float* __restrict__ out,
                       int H, int W) {
    __shared__ __align__(16) float raw[SWY][SWXP];   // 11.9 KB
    __shared__ __align__(16) float pM1[SWY][TW];     // 10 KB
    __shared__ __align__(16) float pM2[SWY][TW];     // 10 KB
    __shared__ __align__(16) float pM3[SWY][TW];     // 10 KB

    const int plane = blockIdx.z;
    const float* xp = x + (size_t)plane * H * W;
    float* op = out + (size_t)plane * H * W;
    const int x0 = blockIdx.x * TW;
    const int y0 = blockIdx.y * TH;
    const int tid = threadIdx.x;

    // ---- load 72x40 raw tile ----
    const bool interior = (x0 >= HALO) && (x0 + TW + HALO <= W) &&
                          (y0 >= HALO) && (y0 + TH + HALO <= H);
    if (interior) {
        const float* src = xp + (size_t)(y0 - HALO) * W + (x0 - HALO);
        #pragma unroll
        for (int k = 0; k < 3; k++) {
            int idx = tid + k * 256;                 // 720 float4 = 2880 floats
            if (idx < 720) {
                int ly = idx / 18;
                int lx = idx - ly * 18;
                float4 v = *(const float4*)(src + (size_t)ly * W + lx * 4);
                *(float4*)&raw[ly][lx * 4] = v;
            }
        }
    } else {
        #pragma unroll
        for (int k = 0; k < 12; k++) {
            int idx = tid + k * 256;
            if (idx < 2880) {
                int ly = idx / SWX;
                int lx = idx - ly * SWX;
                int gy = y0 + ly - HALO;
                int gx = x0 + lx - HALO;
                gy = gy < 0 ? -gy : (gy >= H ? 2 * H - 2 - gy : gy);
                gx = gx < 0 ? -gx : (gx >= W ? 2 * W - 2 - gx : gx);
                raw[ly][lx] = xp[(size_t)gy * W + gx];
            }
        }
    }
    __syncthreads();

    const u64 GG[5] = { pack2(G0f, G0f), pack2(G1f, G1f), pack2(G2f, G2f),
                        pack2(G3f, G3f), pack2(G4f, G4f) };

    // ---- horizontal pass: 40 rows x 32 col-pairs = 1280 units, 5/thread ----
    {
        const int cp  = tid & 31;        // cols 2cp, 2cp+1
        const int rid = tid >> 5;        // 0..7
        #pragma unroll
        for (int rr = 0; rr < 5; rr++) {
            const int r = rid + rr * 8;
            const float* rp = &raw[r][2 * cp];
            float2 L0 = *(const float2*)(rp + 0);
            float2 L1 = *(const float2*)(rp + 2);
            float2 L2 = *(const float2*)(rp + 4);
            float2 L3 = *(const float2*)(rp + 6);
            float2 L4 = *(const float2*)(rp + 8);
            u64 V[9];
            V[0] = pack2(L0.x, L0.y);
            V[1] = pack2(L0.y, L1.x);
            V[2] = pack2(L1.x, L1.y);
            V[3] = pack2(L1.y, L2.x);
            V[4] = pack2(L2.x, L2.y);
            V[5] = pack2(L2.y, L3.x);
            V[6] = pack2(L3.x, L3.y);
            V[7] = pack2(L3.y, L4.x);
            V[8] = pack2(L4.x, L4.y);

            u64 a1, a2, a3;
            {   // j = 0, weight g4
                u64 vv = V[0];
                u64 v2 = mul2(vv, vv), v3 = mul2(v2, vv);
                a1 = mul2(GG[4], vv);
                a2 = mul2(GG[4], v2);
                a3 = mul2(GG[4], v3);
            }
            #pragma unroll
            for (int j = 1; j < KS; j++) {
                u64 vv = V[j];
                u64 v2 = mul2(vv, vv), v3 = mul2(v2, vv);
                const u64 g = GG[j < 4 ? 4 - j : j - 4];
                a1 = fma2(g, vv, a1);
                a2 = fma2(g, v2, a2);
                a3 = fma2(g, v3, a3);
            }

            // packed lanes == adjacent columns: store directly, no transpose
            *(u64*)&pM1[r][2 * cp] = a1;
            *(u64*)&pM2[r][2 * cp] = a2;
            *(u64*)&pM3[r][2 * cp] = a3;
        }
    }
    __syncthreads();

    // ---- vertical pass + epilogue: packed column pairs ----
    const int cp = tid & 31;             // col-pair 0..31
    const int rg = tid >> 5;             // 0..7 -> output rows rg*4 .. rg*4+3

    const u64 B0p  = pack2(B0f, B0f);
    const u64 B1p  = pack2(B1f, B1f);
    const u64 N2B1 = pack2(-2.0f * B1f, -2.0f * B1f);
    const u64 S2p  = pack2(S2f, S2f);

    // two groups of 2 output rows each -> only 6 live u64 accumulators
    #pragma unroll
    for (int gpi = 0; gpi < 2; gpi++) {
        const int rbase = rg * 4 + gpi * 2;   // first output row of group
        u64 m1[2], m2[2], m3[2];
        #pragma unroll
        for (int p = 0; p < 2; p++) { m1[p] = 0ull; m2[p] = 0ull; m3[p] = 0ull; }

        #pragma unroll
        for (int r = 0; r < 10; r++) {        // rows rbase .. rbase+9
            const int row = rbase + r;
            u64 h1 = *(const u64*)&pM1[row][2 * cp];
            u64 h2 = *(const u64*)&pM2[row][2 * cp];
            u64 h3 = *(const u64*)&pM3[row][2 * cp];
            #pragma unroll
            for (int p = 0; p < 2; p++) {
                const int t = r - p;
                if (t >= 0 && t < KS) {       // compile-time pruned
                    const int d = t < 4 ? 4 - t : t - 4;
                    m1[p] = fma2(GG[d], h1, m1[p]);
                    m2[p] = fma2(GG[d], h2, m2[p]);
                    m3[p] = fma2(GG[d], h3, m3[p]);
                }
            }
        }

        #pragma unroll
        for (int p = 0; p < 2; p++) {
            const int row = rbase + p;
            float2 cc = *(const float2*)&raw[row + HALO][2 * cp + HALO];
            u64 c  = pack2(cc.x, cc.y);
            u64 c2 = mul2(c, c);
            u64 p1 = mul2(N2B1, c);                    // -2*b1*c
            u64 q  = fma2(B1p, c2, B0p);               // b0 + b1*c^2

            u64 den = fma2(q, S2p, fma2(p1, m1[p], mul2(B1p, m2[p])));
            u64 num = fma2(q, m1[p], fma2(p1, m2[p], mul2(B1p, m3[p])));

            float n0, n1, d0, d1;
            unpack2(num, n0, n1);
            unpack2(den, d0, d1);
            float2 o = make_float2(__fdividef(n0, d0), __fdividef(n1, d1));
            int oy = y0 + row;
            *(float2*)&op[(size_t)oy * W + x0 + 2 * cp] = o;
        }
    }
}

extern "C" void kernel_launch(void* const* d_in, const int* in_sizes, int n_in,
                              void* d_out, int out_size) {
    const float* x = (const float*)d_in[0];
    float* out = (float*)d_out;
    const int H = 384, W = 384;
    const int planes = out_size / (H * W);   // B*C = 6

    dim3 block(256, 1, 1);
    dim3 grid(W / TW, H / TH, planes);
    bilateral9_kernel<<<grid, block>>>(x, out, H, W);
}

// round 11
// speedup vs baseline: 1.0178x; 1.0178x over previous
#include <cuda_runtime.h>

// Bilateral filter, B=2 C=3 H=W=384, ksize=9, sigma=1.7.
// Density exp ~ minimax linear poly in u=(v-c)^2 on [0,1]; filter = separable
// 9-tap Gaussian moments M1,M2,M3:
//   den = b1*M2 + (-2*b1*c)*M1 + (b0+b1*c^2)*S2
//   num = b1*M3 + (-2*b1*c)*M2 + (b0+b1*c^2)*M1
// Tile 64x32 out, 72x40 halo. Per-moment smem planes (packed col-pair lanes
// store/load as u64, no transposes). Split vertical groups cap live regs at
// 64 -> 4 CTAs/SM; smem carveout raised to 100% so 4x43KB fits.

#define TW   64
#define TH   32
#define HALO 4
#define SWX  72
#define SWXP 76          // raw row stride (16B-aligned)
#define SWY  40
#define KS   9

typedef unsigned long long u64;

// exp(-A*d*d), A = 1/(2*1.7^2)
#define G0f 1.00000000f
#define G1f 0.84112888f
#define G2f 0.50055313f
#define G3f 0.21074770f
#define G4f 0.06277701f
#define S2f 17.8963970f
// minimax linear for exp(-A*u), u in [0,1]
#define B0f 0.99828148f
#define B1f (-0.15887112f)

__device__ __forceinline__ u64 pack2(float lo, float hi) {
    u64 r; asm("mov.b64 %0, {%1,%2};" : "=l"(r) : "f"(lo), "f"(hi)); return r;
}
__device__ __forceinline__ void unpack2(u64 v, float& lo, float& hi) {
    asm("mov.b64 {%0,%1}, %2;" : "=f"(lo), "=f"(hi) : "l"(v));
}
__device__ __forceinline__ u64 fma2(u64 a, u64 b, u64 c) {
    u64 d; asm("fma.rn.f32x2 %0, %1, %2, %3;" : "=l"(d) : "l"(a), "l"(b), "l"(c)); return d;
}
__device__ __forceinline__ u64 mul2(u64 a, u64 b) {
    u64 d; asm("mul.rn.f32x2 %0, %1, %2;" : "=l"(d) : "l"(a), "l"(b)); return d;
}

__global__ __launch_bounds__(256, 4)
void bilateral9_kernel(const float* __restrict__ x, float* __restrict__ out,
                       int H, int W) {
    __shared__ __align__(16) float raw[SWY][SWXP];   // 11.9 KB
    __shared__ __align__(16) float pM1[SWY][TW];     // 10 KB
    __shared__ __align__(16) float pM2[SWY][TW];     // 10 KB
    __shared__ __align__(16) float pM3[SWY][TW];     // 10 KB

    const int plane = blockIdx.z;
    const float* xp = x + (size_t)plane * H * W;
    float* op = out + (size_t)plane * H * W;
    const int x0 = blockIdx.x * TW;
    const int y0 = blockIdx.y * TH;
    const int tid = threadIdx.x;

    // ---- load 72x40 raw tile ----
    const bool interior = (x0 >= HALO) && (x0 + TW + HALO <= W) &&
                          (y0 >= HALO) && (y0 + TH + HALO <= H);
    if (interior) {
        const float* src = xp + (size_t)(y0 - HALO) * W + (x0 - HALO);
        #pragma unroll
        for (int k = 0; k < 3; k++) {
            int idx = tid + k * 256;                 // 720 float4 = 2880 floats
            if (idx < 720) {
                int ly = idx / 18;
                int lx = idx - ly * 18;
                float4 v = *(const float4*)(src + (size_t)ly * W + lx * 4);
                *(float4*)&raw[ly][lx * 4] = v;
            }
        }
    } else {
        #pragma unroll
        for (int k = 0; k < 12; k++) {
            int idx = tid + k * 256;
            if (idx < 2880) {
                int ly = idx / SWX;
                int lx = idx - ly * SWX;
                int gy = y0 + ly - HALO;
                int gx = x0 + lx - HALO;
                gy = gy < 0 ? -gy : (gy >= H ? 2 * H - 2 - gy : gy);
                gx = gx < 0 ? -gx : (gx >= W ? 2 * W - 2 - gx : gx);
                raw[ly][lx] = xp[(size_t)gy * W + gx];
            }
        }
    }
    __syncthreads();

    const u64 GG[5] = { pack2(G0f, G0f), pack2(G1f, G1f), pack2(G2f, G2f),
                        pack2(G3f, G3f), pack2(G4f, G4f) };

    // ---- horizontal pass: 40 rows x 32 col-pairs = 1280 units, 5/thread ----
    {
        const int cp  = tid & 31;        // cols 2cp, 2cp+1
        const int rid = tid >> 5;        // 0..7
        #pragma unroll
        for (int rr = 0; rr < 5; rr++) {
            const int r = rid + rr * 8;
            const float* rp = &raw[r][2 * cp];
            float2 L0 = *(const float2*)(rp + 0);
            float2 L1 = *(const float2*)(rp + 2);
            float2 L2 = *(const float2*)(rp + 4);
            float2 L3 = *(const float2*)(rp + 6);
            float2 L4 = *(const float2*)(rp + 8);
            u64 V[9];
            V[0] = pack2(L0.x, L0.y);
            V[1] = pack2(L0.y, L1.x);
            V[2] = pack2(L1.x, L1.y);
            V[3] = pack2(L1.y, L2.x);
            V[4] = pack2(L2.x, L2.y);
            V[5] = pack2(L2.y, L3.x);
            V[6] = pack2(L3.x, L3.y);
            V[7] = pack2(L3.y, L4.x);
            V[8] = pack2(L4.x, L4.y);

            u64 a1, a2, a3;
            {   // j = 0, weight g4
                u64 vv = V[0];
                u64 v2 = mul2(vv, vv), v3 = mul2(v2, vv);
                a1 = mul2(GG[4], vv);
                a2 = mul2(GG[4], v2);
                a3 = mul2(GG[4], v3);
            }
            #pragma unroll
            for (int j = 1; j < KS; j++) {
                u64 vv = V[j];
                u64 v2 = mul2(vv, vv), v3 = mul2(v2, vv);
                const u64 g = GG[j < 4 ? 4 - j : j - 4];
                a1 = fma2(g, vv, a1);
                a2 = fma2(g, v2, a2);
                a3 = fma2(g, v3, a3);
            }

            // packed lanes == adjacent columns: store directly, no transpose
            *(u64*)&pM1[r][2 * cp] = a1;
            *(u64*)&pM2[r][2 * cp] = a2;
            *(u64*)&pM3[r][2 * cp] = a3;
        }
    }
    __syncthreads();

    // ---- vertical pass + epilogue: packed column pairs ----
    const int cp = tid & 31;             // col-pair 0..31
    const int rg = tid >> 5;             // 0..7 -> output rows rg*4 .. rg*4+3

    const u64 B0p  = pack2(B0f, B0f);
    const u64 B1p  = pack2(B1f, B1f);
    const u64 N2B1 = pack2(-2.0f * B1f, -2.0f * B1f);
    const u64 S2p  = pack2(S2f, S2f);

    // two groups of 2 output rows each -> only 6 live u64 accumulators
    #pragma unroll
    for (int gpi = 0; gpi < 2; gpi++) {
        const int rbase = rg * 4 + gpi * 2;   // first output row of group
        u64 m1[2], m2[2], m3[2];
        #pragma unroll
        for (int p = 0; p < 2; p++) { m1[p] = 0ull; m2[p] = 0ull; m3[p] = 0ull; }

        #pragma unroll
        for (int r = 0; r < 10; r++) {        // rows rbase .. rbase+9
            const int row = rbase + r;
            u64 h1 = *(const u64*)&pM1[row][2 * cp];
            u64 h2 = *(const u64*)&pM2[row][2 * cp];
            u64 h3 = *(const u64*)&pM3[row][2 * cp];
            #pragma unroll
            for (int p = 0; p < 2; p++) {
                const int t = r - p;
                if (t >= 0 && t < KS) {       // compile-time pruned
                    const int d = t < 4 ? 4 - t : t - 4;
                    m1[p] = fma2(GG[d], h1, m1[p]);
                    m2[p] = fma2(GG[d], h2, m2[p]);
                    m3[p] = fma2(GG[d], h3, m3[p]);
                }
            }
        }

        #pragma unroll
        for (int p = 0; p < 2; p++) {
            const int row = rbase + p;
            float2 cc = *(const float2*)&raw[row + HALO][2 * cp + HALO];
            u64 c  = pack2(cc.x, cc.y);
            u64 c2 = mul2(c, c);
            u64 p1 = mul2(N2B1, c);                    // -2*b1*c
            u64 q  = fma2(B1p, c2, B0p);               // b0 + b1*c^2

            u64 den = fma2(q, S2p, fma2(p1, m1[p], mul2(B1p, m2[p])));
            u64 num = fma2(q, m1[p], fma2(p1, m2[p], mul2(B1p, m3[p])));

            float n0, n1, d0, d1;
            unpack2(num, n0, n1);
            unpack2(den, d0, d1);
            float2 o = make_float2(__fdividef(n0, d0), __fdividef(n1, d1));
            int oy = y0 + row;
            *(float2*)&op[(size_t)oy * W + x0 + 2 * cp] = o;
        }
    }
}

extern "C" void kernel_launch(void* const* d_in, const int* in_sizes, int n_in,
                              void* d_out, int out_size) {
    const float* x = (const float*)d_in[0];
    float* out = (float*)d_out;
    const int H = 384, W = 384;
    const int planes = out_size / (H * W);   // B*C = 6

    // Ask for maximum shared-memory carveout so 4 CTAs x 43KB fit per SM.
    // Idempotent host-side attribute set; no allocation, capture-legal.
    cudaFuncSetAttribute(bilateral9_kernel,
                         cudaFuncAttributePreferredSharedMemoryCarveout, 100);

    dim3 block(256, 1, 1);
    dim3 grid(W / TW, H / TH, planes);
    bilateral9_kernel<<<grid, block>>>(x, out, H, W);
}